// round 6
// baseline (speedup 1.0000x reference)
#include <cuda_runtime.h>
#include <cstdint>

// Conv2d N=16,C=128,H=W=56,K=128,3x3,pad1 as 9 shifted GEMMs using
// mma.sync.m16n8k8 tf32. CTA = 128k x 112 pos (2 rows x 56 w), 8 warps.
// 3-slot cp.async W ring + double-buffered cp.async X; ONE barrier/stage;
// register-double-buffered fragments so LDS(s,kk+1) overlaps HMMA(s,kk).
// X layout [kk][lq][row][w][h] -> B fragment pair = one LDS.64 (bank-opt).

typedef uint32_t u32;

#define X_ELEMS (4 * 1856)           // 7424 u32: [kk:4][lq:4 x464][row:4 x116][w:58 x2][h:2]
#define W_ELEMS (128 * 36)           // 4608 u32 per W slot ([128k][36 pad])
#define XB(i)   ((i) * X_ELEMS)
#define WB(i)   (2 * X_ELEMS + (i) * W_ELEMS)
#define SMEM_BYTES ((2 * X_ELEMS + 3 * W_ELEMS) * 4)   // 114688 = 112KB

__device__ u32 g_Wt[36 * 4096];      // [cg*9+rs][k][c32], tf32 bits (RNA)

__device__ __forceinline__ u32 f2tf(float f) {
    u32 r; asm("cvt.rna.tf32.f32 %0, %1;" : "=r"(r) : "f"(f)); return r;
}

__global__ void prep_weights(const float* __restrict__ wt) {
    int idx = blockIdx.x * 256 + threadIdx.x;
    if (idx >= 36 * 4096) return;
    int slab = idx >> 12;
    int k = (idx >> 5) & 127;
    int c = idx & 31;
    int cg = slab / 9, rs = slab % 9;
    g_Wt[idx] = f2tf(wt[(size_t)k * 1152 + (size_t)(cg * 32 + c) * 9 + rs]);
}

__global__ __launch_bounds__(256, 2)
void conv_mma(const float* __restrict__ in,
              const float* __restrict__ bias,
              float* __restrict__ out)
{
    extern __shared__ u32 sm[];
    u32 sbase;
    asm("{ .reg .u64 t; cvta.to.shared.u64 t, %1; cvt.u32.u64 %0, t; }"
        : "=r"(sbase) : "l"(sm));

    const int tid = threadIdx.x;
    const int wid = tid >> 5, lid = tid & 31;
    const int lq = lid & 3, g = lid >> 2;
    const int m0 = (wid & 3) * 32;        // warp m offset (k channels)
    const int wn = wid >> 2;              // warp output row (0/1)

    const int img = blockIdx.x / 28;
    const int h0  = (blockIdx.x % 28) * 2;
    const float* in_n = in + (size_t)img * 401408;

    float acc[2][7][4];
    #pragma unroll
    for (int mt = 0; mt < 2; mt++)
        #pragma unroll
        for (int nt = 0; nt < 7; nt++)
            #pragma unroll
            for (int q = 0; q < 4; q++) acc[mt][nt][q] = 0.f;

    // ---- async X loader: predicated zero-fill cp.async into pipelined layout ----
    auto loadX = [&](int cg, int xb) {
        const u32 dbase = sbase + XB(xb) * 4;
        for (int idx = tid; idx < X_ELEMS; idx += 256) {
            int wl  = idx % 58;
            int t   = idx / 58;
            int row = t & 3;
            int c   = t >> 2;
            int hin = h0 - 1 + row;
            int win = wl - 1;
            bool v = ((unsigned)hin < 56u) & ((unsigned)win < 56u);
            const float* src = v ? (in_n + (size_t)(cg * 32 + c) * 3136
                                    + hin * 56 + win)
                                 : in_n;
            int sz = v ? 4 : 0;
            int dw = (c >> 3) * 1856 + (c & 3) * 464 + row * 116 + wl * 2
                     + ((c >> 2) & 1);
            u32 dst = dbase + dw * 4;
            asm volatile("cp.async.ca.shared.global [%0], [%1], 4, %2;"
                         :: "r"(dst), "l"(src), "r"(sz) : "memory");
        }
    };

    // ---- async W loader: one 16KB slab into ring slot ----
    auto prefW = [&](int s, int slot) {
        const u32* src = g_Wt + (size_t)s * 4096;
        const u32 dstb = sbase + WB(slot) * 4;
        #pragma unroll
        for (int j = 0; j < 4; j++) {
            int chunk = tid + j * 256;
            int k = chunk >> 3, cq = chunk & 7;
            u32 dst = dstb + k * 144 + cq * 16;
            asm volatile("cp.async.ca.shared.global [%0], [%1], 16;"
                         :: "r"(dst), "l"(src + chunk * 4) : "memory");
        }
        asm volatile("cp.async.commit_group;" ::: "memory");
    };

    // fragment double buffers
    u32 a[2][2][4], b[2][7][2];

    auto ldA = [&](int slot, int kk, int buf) {
        const u32* p0 = sm + WB(slot) + (m0 + g) * 36 + lq + kk * 8;
        #pragma unroll
        for (int mt = 0; mt < 2; mt++) {
            const u32* p = p0 + mt * 576;
            a[buf][mt][0] = p[0];   a[buf][mt][1] = p[288];
            a[buf][mt][2] = p[4];   a[buf][mt][3] = p[292];
        }
    };
    auto ldB = [&](int s, int kk, int buf) {
        const int rs = s % 9;
        const int xb = (s / 9) & 1;
        const u32* p0 = sm + XB(xb) + lq * 464 + (wn + rs / 3) * 116
                        + (g + rs % 3) * 2 + kk * 1856;
        #pragma unroll
        for (int nt = 0; nt < 7; nt++) {
            uint2 v = *reinterpret_cast<const uint2*>(p0 + nt * 16);
            b[buf][nt][0] = v.x;
            b[buf][nt][1] = v.y;
        }
    };

    // ---- prologue ----
    loadX(0, 0);           // rides group 0
    prefW(0, 0);           // group 0
    prefW(1, 1);           // group 1
    asm volatile("cp.async.wait_group 1;" ::: "memory");   // group 0 done
    __syncthreads();
    ldA(0, 0, 0);
    ldB(0, 0, 0);
    int cur = 0;

    for (int s = 0; s < 36; s++) {
        if (s > 0) {
            asm volatile("cp.async.wait_group 0;" ::: "memory");
            __syncthreads();
        }
        if (s + 2 < 36) {
            if (s % 9 == 5) loadX(s / 9 + 1, (s / 9 + 1) & 1);
            prefW(s + 2, (s + 2) % 3);
        }

        #pragma unroll
        for (int kk = 0; kk < 4; kk++) {
            const int nb = cur ^ 1;
            if (kk < 3) {
                ldA(s % 3, kk + 1, nb);
                ldB(s, kk + 1, nb);
            } else {
                // prefetch first fragments of next stage (slot ready since
                // group s+1 completed at this stage's wait_group 0).
                // s==35: reads in-range garbage, never used.
                ldA((s + 1) % 3, 0, nb);
                ldB(s + 1 < 36 ? s + 1 : 35, 0, nb);
            }
            #pragma unroll
            for (int mt = 0; mt < 2; mt++)
                #pragma unroll
                for (int nt = 0; nt < 7; nt++)
                    asm volatile(
                        "mma.sync.aligned.m16n8k8.row.col.f32.tf32.tf32.f32 "
                        "{%0,%1,%2,%3}, {%4,%5,%6,%7}, {%8,%9}, {%0,%1,%2,%3};"
                        : "+f"(acc[mt][nt][0]), "+f"(acc[mt][nt][1]),
                          "+f"(acc[mt][nt][2]), "+f"(acc[mt][nt][3])
                        : "r"(a[cur][mt][0]), "r"(a[cur][mt][1]),
                          "r"(a[cur][mt][2]), "r"(a[cur][mt][3]),
                          "r"(b[cur][nt][0]), "r"(b[cur][nt][1]));
            cur = nb;
        }
    }

    // ---- epilogue: direct STG.64 + bias ----
    #pragma unroll
    for (int mt = 0; mt < 2; mt++)
        #pragma unroll
        for (int h = 0; h < 2; h++) {
            const int k = m0 + mt * 16 + h * 8 + g;
            const float bv = __ldg(&bias[k]);
            float* op = out + (size_t)img * 401408 + (size_t)k * 3136
                        + (h0 + wn) * 56 + lq * 2;
            #pragma unroll
            for (int nt = 0; nt < 7; nt++) {
                float2 v;
                v.x = acc[mt][nt][2 * h + 0] + bv;
                v.y = acc[mt][nt][2 * h + 1] + bv;
                *reinterpret_cast<float2*>(op + nt * 8) = v;
            }
        }
}

extern "C" void kernel_launch(void* const* d_in, const int* in_sizes, int n_in,
                              void* d_out, int out_size)
{
    const float* input  = (const float*)d_in[0];
    const float* weight = (const float*)d_in[1];
    const float* bias   = (const float*)d_in[2];
    float* out = (float*)d_out;

    cudaFuncSetAttribute(conv_mma, cudaFuncAttributeMaxDynamicSharedMemorySize,
                         SMEM_BYTES);

    prep_weights<<<(36 * 4096 + 255) / 256, 256>>>(weight);
    conv_mma<<<448, 256, SMEM_BYTES>>>(input, bias, out);
}

// round 7
// speedup vs baseline: 1.1110x; 1.1110x over previous
#include <cuda_runtime.h>
#include <cstdint>

// Conv2d N=16,C=128,H=W=56,K=128,3x3,pad1 as 9 shifted GEMMs using
// mma.sync.m16n8k8 tf32. CTA = 128k x 112 pos (2 rows x 56 w), 8 warps.
// R5 pipeline (3-slot cp.async W ring, double-buffered cp.async X, one
// barrier/stage) + vectorized fragment loads:
//   A: prep kernel emits per-lane 16B fragment groups  -> LDS.128
//   B: X interleaved [kk][c&3(488)][row][w][c-hi]      -> LDS.64, bank-free

typedef uint32_t u32;

#define X_ELEMS 7808                 // 4 kk x 1952  ([c&3:488][row:116][w:2][hi])
#define W_ELEMS 4096                 // [mgrp:4][mt:2][kk:4][lane:32][4]
#define XB(i)   ((i) * X_ELEMS)
#define WB(i)   (2 * X_ELEMS + (i) * W_ELEMS)
#define SMEM_BYTES ((2 * X_ELEMS + 3 * W_ELEMS) * 4)   // 111616

__device__ u32 g_Wt[36 * 4096];      // [cg*9+rs] fragment-ordered slabs (tf32 RNA)

__device__ __forceinline__ u32 f2tf(float f) {
    u32 r; asm("cvt.rna.tf32.f32 %0, %1;" : "=r"(r) : "f"(f)); return r;
}

__global__ void prep_weights(const float* __restrict__ wt) {
    int idx = blockIdx.x * 256 + threadIdx.x;
    if (idx >= 36 * 4096) return;
    int slab   = idx >> 12;
    int within = idx & 4095;
    int vi   = within & 3;
    int lane = (within >> 2) & 31;
    int kk   = (within >> 7) & 3;
    int mt   = (within >> 9) & 1;
    int mgrp = (within >> 10) & 3;
    int k = mgrp * 32 + mt * 16 + (lane >> 2) + (vi & 1) * 8;
    int c = kk * 8 + (lane & 3) + (vi >> 1) * 4;
    int cg = slab / 9, rs = slab % 9;
    g_Wt[idx] = f2tf(wt[(size_t)k * 1152 + (size_t)(cg * 32 + c) * 9 + rs]);
}

__global__ __launch_bounds__(256, 2)
void conv_mma(const float* __restrict__ in,
              const float* __restrict__ bias,
              float* __restrict__ out)
{
    extern __shared__ u32 sm[];
    u32 sbase;
    asm("{ .reg .u64 t; cvta.to.shared.u64 t, %1; cvt.u32.u64 %0, t; }"
        : "=r"(sbase) : "l"(sm));

    const int tid = threadIdx.x;
    const int wid = tid >> 5, lid = tid & 31;
    const int lq = lid & 3, g = lid >> 2;
    const int mgrp = wid & 3;             // warp m group (32 k each)
    const int m0 = mgrp * 32;
    const int wn = wid >> 2;              // warp output row (0/1)

    const int img = blockIdx.x / 28;
    const int h0  = (blockIdx.x % 28) * 2;
    const float* in_n = in + (size_t)img * 401408;

    float acc[2][7][4];
    #pragma unroll
    for (int mt = 0; mt < 2; mt++)
        #pragma unroll
        for (int nt = 0; nt < 7; nt++)
            #pragma unroll
            for (int q = 0; q < 4; q++) acc[mt][nt][q] = 0.f;

    // ---- async X loader: predicated zero-fill cp.async, interleaved layout ----
    auto loadX = [&](int cg, int xb) {
        const u32 dbase = sbase + XB(xb) * 4;
        for (int idx = tid; idx < 32 * 4 * 58; idx += 256) {
            int wl  = idx % 58;
            int t   = idx / 58;
            int row = t & 3;
            int c   = t >> 2;
            int hin = h0 - 1 + row;
            int win = wl - 1;
            bool v = ((unsigned)hin < 56u) & ((unsigned)win < 56u);
            const float* src = v ? (in_n + (size_t)(cg * 32 + c) * 3136
                                    + hin * 56 + win)
                                 : in_n;
            int sz = v ? 4 : 0;
            int dw = (c >> 3) * 1952 + (c & 3) * 488 + row * 116 + wl * 2
                     + ((c >> 2) & 1);
            u32 dst = dbase + dw * 4;
            asm volatile("cp.async.ca.shared.global [%0], [%1], 4, %2;"
                         :: "r"(dst), "l"(src), "r"(sz) : "memory");
        }
    };

    // ---- async W loader: linear 16KB slab copy into ring slot ----
    auto prefW = [&](int s, int slot) {
        const u32* src = g_Wt + (size_t)s * 4096;
        const u32 dstb = sbase + WB(slot) * 4;
        #pragma unroll
        for (int j = 0; j < 4; j++) {
            int chunk = tid + j * 256;             // 0..1023, 16B each
            asm volatile("cp.async.ca.shared.global [%0], [%1], 16;"
                         :: "r"(dstb + chunk * 16), "l"(src + chunk * 4)
                         : "memory");
        }
        asm volatile("cp.async.commit_group;" ::: "memory");
    };

    // ---- prologue: group0 = X(cg0)+W(0); group1 = W(1) ----
    loadX(0, 0);
    prefW(0, 0);
    prefW(1, 1);

    for (int s = 0; s < 36; s++) {
        if (s < 35) asm volatile("cp.async.wait_group 1;" ::: "memory");
        else        asm volatile("cp.async.wait_group 0;" ::: "memory");
        __syncthreads();   // groups <= s visible; stage s-1 consumers done

        if (s + 2 < 36) {
            if (s % 9 == 5) loadX(s / 9 + 1, (s / 9 + 1) & 1);
            prefW(s + 2, (s + 2) % 3);
        }

        const int rs = s % 9;
        const u32* Wb = sm + WB(s % 3) + mgrp * 1024 + lid * 4;
        const u32* Bb = sm + XB((s / 9) & 1) + lq * 488
                        + (wn + rs / 3) * 116 + (g + rs % 3) * 2;

        #pragma unroll
        for (int kk = 0; kk < 4; kk++) {
            u32 a[2][4], b[7][2];
            #pragma unroll
            for (int mt = 0; mt < 2; mt++) {
                uint4 v = *reinterpret_cast<const uint4*>(
                              Wb + mt * 512 + kk * 128);
                a[mt][0] = v.x; a[mt][1] = v.y; a[mt][2] = v.z; a[mt][3] = v.w;
            }
            #pragma unroll
            for (int nt = 0; nt < 7; nt++) {
                uint2 v = *reinterpret_cast<const uint2*>(
                              Bb + kk * 1952 + nt * 16);
                b[nt][0] = v.x;
                b[nt][1] = v.y;
            }
            #pragma unroll
            for (int mt = 0; mt < 2; mt++)
                #pragma unroll
                for (int nt = 0; nt < 7; nt++)
                    asm volatile(
                        "mma.sync.aligned.m16n8k8.row.col.f32.tf32.tf32.f32 "
                        "{%0,%1,%2,%3}, {%4,%5,%6,%7}, {%8,%9}, {%0,%1,%2,%3};"
                        : "+f"(acc[mt][nt][0]), "+f"(acc[mt][nt][1]),
                          "+f"(acc[mt][nt][2]), "+f"(acc[mt][nt][3])
                        : "r"(a[mt][0]), "r"(a[mt][1]), "r"(a[mt][2]), "r"(a[mt][3]),
                          "r"(b[nt][0]), "r"(b[nt][1]));
        }
        // no trailing barrier: next iter's top barrier protects slot reuse
    }

    // ---- epilogue: direct STG.64 + bias ----
    #pragma unroll
    for (int mt = 0; mt < 2; mt++)
        #pragma unroll
        for (int h = 0; h < 2; h++) {
            const int k = m0 + mt * 16 + h * 8 + g;
            const float bv = __ldg(&bias[k]);
            float* op = out + (size_t)img * 401408 + (size_t)k * 3136
                        + (h0 + wn) * 56 + lq * 2;
            #pragma unroll
            for (int nt = 0; nt < 7; nt++) {
                float2 v;
                v.x = acc[mt][nt][2 * h + 0] + bv;
                v.y = acc[mt][nt][2 * h + 1] + bv;
                *reinterpret_cast<float2*>(op + nt * 8) = v;
            }
        }
}

extern "C" void kernel_launch(void* const* d_in, const int* in_sizes, int n_in,
                              void* d_out, int out_size)
{
    const float* input  = (const float*)d_in[0];
    const float* weight = (const float*)d_in[1];
    const float* bias   = (const float*)d_in[2];
    float* out = (float*)d_out;

    cudaFuncSetAttribute(conv_mma, cudaFuncAttributeMaxDynamicSharedMemorySize,
                         SMEM_BYTES);

    prep_weights<<<(36 * 4096 + 255) / 256, 256>>>(weight);
    conv_mma<<<448, 256, SMEM_BYTES>>>(input, bias, out);
}

// round 8
// speedup vs baseline: 1.8677x; 1.6812x over previous
#include <cuda_runtime.h>
#include <cstdint>

// Conv2d N=16,C=128,H=W=56,K=128,3x3,pad1 as 9 shifted GEMMs using
// mma.sync.m16n8k16.f32.f16.f16.f32 (base PTX). fp16 mantissa == tf32
// mantissa (10 bits), RN on both operands; K=16/instr halves HMMA count.
// CTA = 128k x 112 pos (2 rows x 56 w), 8 warps. 3-slot cp.async W ring,
// double-buffered X (LDG->cvt->STS), one barrier/stage.
//   A: prep emits per-lane 16B fragment groups              -> LDS.128
//   B: X half2 units [kk][lq(488)][row(122)][w*2][hi]       -> LDS.64 opt

typedef uint32_t u32;

#define X_ELEMS 3904                 // u32 half2 units: 2kk x 4lq x 4row x 122
#define W_ELEMS 2048                 // u32: [mgrp:4][mt:2][kk:2][lane:32][4]
#define XB(i)   ((i) * X_ELEMS)
#define WB(i)   (2 * X_ELEMS + (i) * W_ELEMS)
#define SMEM_BYTES ((2 * X_ELEMS + 3 * W_ELEMS) * 4)   // 55808

__device__ u32 g_Wh[36 * 2048];      // fragment-ordered fp16x2 slabs

__global__ void prep_weights(const float* __restrict__ wt) {
    int idx = blockIdx.x * 256 + threadIdx.x;
    if (idx >= 36 * 2048) return;
    int slab   = idx >> 11;
    int within = idx & 2047;
    int vi   = within & 3;           // a-reg index a0..a3
    int lane = (within >> 2) & 31;
    int kk   = (within >> 7) & 1;
    int mt   = (within >> 8) & 1;
    int mgrp = (within >> 9) & 3;
    int cg = slab / 9, rs = slab % 9;
    int k  = mgrp * 32 + mt * 16 + (lane >> 2) + (vi & 1) * 8;
    int c0 = cg * 32 + kk * 16 + (lane & 3) * 2 + (vi >> 1) * 8;
    float v0 = wt[(size_t)k * 1152 + (size_t)c0 * 9 + rs];
    float v1 = wt[(size_t)k * 1152 + (size_t)(c0 + 1) * 9 + rs];
    u32 p;
    asm("cvt.rn.f16x2.f32 %0, %1, %2;" : "=r"(p) : "f"(v1), "f"(v0));
    g_Wh[idx] = p;
}

__global__ __launch_bounds__(256, 2)
void conv_mma(const float* __restrict__ in,
              const float* __restrict__ bias,
              float* __restrict__ out)
{
    extern __shared__ u32 sm[];
    u32 sbase;
    asm("{ .reg .u64 t; cvta.to.shared.u64 t, %1; cvt.u32.u64 %0, t; }"
        : "=r"(sbase) : "l"(sm));

    const int tid = threadIdx.x;
    const int wid = tid >> 5, lid = tid & 31;
    const int lq = lid & 3, g = lid >> 2;
    const int mgrp = wid & 3;             // warp m group (32 k each)
    const int m0 = mgrp * 32;
    const int wn = wid >> 2;              // warp output row (0/1)

    const int img = blockIdx.x / 28;
    const int h0  = (blockIdx.x % 28) * 2;
    const float* in_n = in + (size_t)img * 401408;

    float acc[2][7][4];
    #pragma unroll
    for (int mt = 0; mt < 2; mt++)
        #pragma unroll
        for (int nt = 0; nt < 7; nt++)
            #pragma unroll
            for (int q = 0; q < 4; q++) acc[mt][nt][q] = 0.f;

    // ---- X loader: LDG fp32 -> cvt.rn.f16x2 -> STS (once per element) ----
    auto loadX = [&](int cg, int xb) {
        for (int idx = tid; idx < 3712; idx += 256) {
            int wl  = idx % 58;
            int t   = idx / 58;
            int row = t & 3;
            int hi  = (t >> 2) & 1;
            int lq_ = (t >> 3) & 3;
            int kk_ = t >> 5;
            int hin = h0 - 1 + row;
            int win = wl - 1;
            int c0  = cg * 32 + kk_ * 16 + lq_ * 2 + hi * 8;
            float v0 = 0.f, v1 = 0.f;
            if (((unsigned)hin < 56u) & ((unsigned)win < 56u)) {
                const float* p = in_n + (size_t)c0 * 3136 + hin * 56 + win;
                v0 = __ldg(p);
                v1 = __ldg(p + 3136);
            }
            u32 pk;
            asm("cvt.rn.f16x2.f32 %0, %1, %2;" : "=r"(pk) : "f"(v1), "f"(v0));
            sm[XB(xb) + ((kk_ * 4 + lq_) * 4 + row) * 122 + wl * 2 + hi] = pk;
        }
    };

    // ---- async W loader: linear 8KB slab copy into ring slot ----
    auto prefW = [&](int s, int slot) {
        const u32* src = g_Wh + (size_t)s * 2048;
        const u32 dstb = sbase + WB(slot) * 4;
        #pragma unroll
        for (int j = 0; j < 2; j++) {
            int chunk = tid + j * 256;             // 0..511, 16B each
            asm volatile("cp.async.ca.shared.global [%0], [%1], 16;"
                         :: "r"(dstb + chunk * 16), "l"(src + chunk * 4)
                         : "memory");
        }
        asm volatile("cp.async.commit_group;" ::: "memory");
    };

    // ---- prologue ----
    loadX(0, 0);
    prefW(0, 0);
    prefW(1, 1);

    for (int s = 0; s < 36; s++) {
        if (s < 35) asm volatile("cp.async.wait_group 1;" ::: "memory");
        else        asm volatile("cp.async.wait_group 0;" ::: "memory");
        __syncthreads();   // W(s) + current X visible; prior consumers done

        if (s + 2 < 36) prefW(s + 2, (s + 2) % 3);
        if (s % 9 == 5 && s / 9 + 1 < 4) loadX(s / 9 + 1, (s / 9 + 1) & 1);

        const int rs = s % 9;
        const u32* Wb = sm + WB(s % 3) + mgrp * 512 + lid * 4;
        const u32* Bb = sm + XB((s / 9) & 1) + lq * 488
                        + (wn + rs / 3) * 122 + (g + rs % 3) * 2;

        #pragma unroll
        for (int kk = 0; kk < 2; kk++) {
            u32 a[2][4], b[7][2];
            #pragma unroll
            for (int mt = 0; mt < 2; mt++) {
                uint4 v = *reinterpret_cast<const uint4*>(
                              Wb + mt * 256 + kk * 128);
                a[mt][0] = v.x; a[mt][1] = v.y; a[mt][2] = v.z; a[mt][3] = v.w;
            }
            #pragma unroll
            for (int nt = 0; nt < 7; nt++) {
                uint2 v = *reinterpret_cast<const uint2*>(
                              Bb + kk * 1952 + nt * 16);
                b[nt][0] = v.x;
                b[nt][1] = v.y;
            }
            #pragma unroll
            for (int mt = 0; mt < 2; mt++)
                #pragma unroll
                for (int nt = 0; nt < 7; nt++)
                    asm volatile(
                        "mma.sync.aligned.m16n8k16.row.col.f32.f16.f16.f32 "
                        "{%0,%1,%2,%3}, {%4,%5,%6,%7}, {%8,%9}, {%0,%1,%2,%3};"
                        : "+f"(acc[mt][nt][0]), "+f"(acc[mt][nt][1]),
                          "+f"(acc[mt][nt][2]), "+f"(acc[mt][nt][3])
                        : "r"(a[mt][0]), "r"(a[mt][1]), "r"(a[mt][2]), "r"(a[mt][3]),
                          "r"(b[nt][0]), "r"(b[nt][1]));
        }
    }

    // ---- epilogue: direct STG.64 + bias ----
    #pragma unroll
    for (int mt = 0; mt < 2; mt++)
        #pragma unroll
        for (int h = 0; h < 2; h++) {
            const int k = m0 + mt * 16 + h * 8 + g;
            const float bv = __ldg(&bias[k]);
            float* op = out + (size_t)img * 401408 + (size_t)k * 3136
                        + (h0 + wn) * 56 + lq * 2;
            #pragma unroll
            for (int nt = 0; nt < 7; nt++) {
                float2 v;
                v.x = acc[mt][nt][2 * h + 0] + bv;
                v.y = acc[mt][nt][2 * h + 1] + bv;
                *reinterpret_cast<float2*>(op + nt * 8) = v;
            }
        }
}

extern "C" void kernel_launch(void* const* d_in, const int* in_sizes, int n_in,
                              void* d_out, int out_size)
{
    const float* input  = (const float*)d_in[0];
    const float* weight = (const float*)d_in[1];
    const float* bias   = (const float*)d_in[2];
    float* out = (float*)d_out;

    cudaFuncSetAttribute(conv_mma, cudaFuncAttributeMaxDynamicSharedMemorySize,
                         SMEM_BYTES);

    prep_weights<<<(36 * 2048 + 255) / 256, 256>>>(weight);
    conv_mma<<<448, 256, SMEM_BYTES>>>(input, bias, out);
}